// round 2
// baseline (speedup 1.0000x reference)
#include <cuda_runtime.h>
#include <math.h>

// ---------------------------------------------------------------------------
// Problem shape (fixed by the reference setup_inputs)
// ---------------------------------------------------------------------------
#define BB 4
#define SS 4096
#define DD 1024
#define HH 4096
#define MM (BB * SS)          // 16384 rows
#define NCHUNK 64
#define CHLEN (SS / NCHUNK)   // 64
#define NCH (BB * DD)         // 4096 scan channels

// ---------------------------------------------------------------------------
// Scratch (static __device__ arrays: no allocation at runtime)
// ---------------------------------------------------------------------------
__device__ float g_normed[(size_t)MM * DD];   // RMS(x) / RMS(x1)
__device__ float g_k     [(size_t)MM * DD];   // k, later reused for r*wkv
__device__ float g_kv    [(size_t)MM * DD];   // k*v
__device__ float g_r     [(size_t)MM * DD];   // sigmoid(r)
__device__ float g_x1    [(size_t)MM * DD];   // x + mixer_scale*mixer_out
__device__ float g_h2    [(size_t)MM * HH];   // leaky(z)^2
__device__ float g_carry  [NCHUNK * NCH];
__device__ float g_carryin[NCHUNK * NCH];

// ---------------------------------------------------------------------------
// RMS norm: one block per row, 256 threads, 4 floats/thread (D=1024)
// ---------------------------------------------------------------------------
__global__ void rms_kernel(const float* __restrict__ x, float* __restrict__ out)
{
    const int row = blockIdx.x;
    const float4* xr = (const float4*)(x + (size_t)row * DD);
    float4 a = xr[threadIdx.x];
    float ss = a.x * a.x + a.y * a.y + a.z * a.z + a.w * a.w;
    #pragma unroll
    for (int o = 16; o > 0; o >>= 1)
        ss += __shfl_xor_sync(0xffffffffu, ss, o);
    __shared__ float sred[8];
    __shared__ float s_scale;
    if ((threadIdx.x & 31) == 0) sred[threadIdx.x >> 5] = ss;
    __syncthreads();
    if (threadIdx.x == 0) {
        float t = 0.f;
        #pragma unroll
        for (int i = 0; i < 8; i++) t += sred[i];
        s_scale = rsqrtf(t * (1.0f / DD) + 1e-6f);
    }
    __syncthreads();
    const float sc = s_scale;
    float4 o4 = make_float4(a.x * sc, a.y * sc, a.z * sc, a.w * sc);
    ((float4*)(out + (size_t)row * DD))[threadIdx.x] = o4;
}

// ---------------------------------------------------------------------------
// SGEMM: C[M,N] = epi( A[M,K] @ W[N,K]^T )
// 128x128 tile, BK=8, 256 threads, 8x8 per thread, float4 smem fragments.
// Epilogues:
//   0 = plain            C = z
//   1 = mul              C = z * aux           (aux: [M,N])   -> kv = v*k
//   2 = sigmoid          C = 1/(1+exp(-z))
//   3 = leaky(0.5)^2     t = z>0 ? z : 0.5z;  C = t*t
//   4 = residual         C = aux + scale[col]*z
// ---------------------------------------------------------------------------
template <int EPI>
__global__ __launch_bounds__(256, 2)
void sgemm_kernel(const float* __restrict__ A, const float* __restrict__ W,
                  float* __restrict__ C, int M, int N, int K,
                  const float* __restrict__ aux, const float* __restrict__ scale)
{
    __shared__ float As[8][128];
    __shared__ float Bs[8][128];

    const int tid = threadIdx.x;
    const int loadRow = tid >> 1;          // 0..127
    const int loadCol = (tid & 1) << 2;    // 0 or 4
    const size_t aBase = (size_t)(blockIdx.y * 128 + loadRow) * K + loadCol;
    const size_t wBase = (size_t)(blockIdx.x * 128 + loadRow) * K + loadCol;
    const int tx = (tid & 15) << 3;        // col offset in tile, 0..120
    const int ty = (tid >> 4) << 3;        // row offset in tile, 0..120

    float acc[8][8];
    #pragma unroll
    for (int i = 0; i < 8; i++)
        #pragma unroll
        for (int j = 0; j < 8; j++) acc[i][j] = 0.f;

    for (int k0 = 0; k0 < K; k0 += 8) {
        float4 a4 = *(const float4*)(A + aBase + k0);
        float4 b4 = *(const float4*)(W + wBase + k0);
        As[loadCol + 0][loadRow] = a4.x;
        As[loadCol + 1][loadRow] = a4.y;
        As[loadCol + 2][loadRow] = a4.z;
        As[loadCol + 3][loadRow] = a4.w;
        Bs[loadCol + 0][loadRow] = b4.x;
        Bs[loadCol + 1][loadRow] = b4.y;
        Bs[loadCol + 2][loadRow] = b4.z;
        Bs[loadCol + 3][loadRow] = b4.w;
        __syncthreads();
        #pragma unroll
        for (int kk = 0; kk < 8; kk++) {
            // float4 fragment loads: LDS.128, conflict-free phases
            float4 a0 = *(const float4*)&As[kk][ty];
            float4 a1 = *(const float4*)&As[kk][ty + 4];
            float4 b0 = *(const float4*)&Bs[kk][tx];
            float4 b1 = *(const float4*)&Bs[kk][tx + 4];
            float ar[8] = {a0.x, a0.y, a0.z, a0.w, a1.x, a1.y, a1.z, a1.w};
            float br[8] = {b0.x, b0.y, b0.z, b0.w, b1.x, b1.y, b1.z, b1.w};
            #pragma unroll
            for (int i = 0; i < 8; i++)
                #pragma unroll
                for (int j = 0; j < 8; j++)
                    acc[i][j] += ar[i] * br[j];
        }
        __syncthreads();
    }

    const int rowBase = blockIdx.y * 128 + ty;
    const int colBase = blockIdx.x * 128 + tx;
    #pragma unroll
    for (int i = 0; i < 8; i++) {
        const size_t ro = (size_t)(rowBase + i) * N + colBase;
        #pragma unroll
        for (int j = 0; j < 8; j++) {
            float z = acc[i][j];
            float o;
            if (EPI == 0) {
                o = z;
            } else if (EPI == 1) {
                o = z * aux[ro + j];
            } else if (EPI == 2) {
                o = 1.0f / (1.0f + expf(-z));
            } else if (EPI == 3) {
                float t = z > 0.f ? z : 0.5f * z;
                o = t * t;
            } else {
                o = aux[ro + j] + scale[colBase + j] * z;
            }
            C[ro + j] = o;
        }
    }
}

// ---------------------------------------------------------------------------
// Chunked linear scan:  s_t = ew*s_{t-1} + kv_t ;  wkv_t = s_{t-1} + eu*kv_t
// Pass 1: per (chunk, channel) carry-out with zero carry-in.
// Pass 2: per channel, serial scan over NCHUNK carries (multiplier ew^CHLEN).
// Pass 3: per (chunk, channel) recompute with carry-in, write r*wkv.
// ---------------------------------------------------------------------------
__global__ void scan_pass1(const float* __restrict__ kv,
                           const float* __restrict__ td,
                           float* __restrict__ carry)
{
    const int idx = blockIdx.x * blockDim.x + threadIdx.x; // c*NCH + b*DD + d
    const int ch = idx & (NCH - 1);
    const int c  = idx >> 12;                // NCH = 4096 = 2^12
    const int d  = ch & (DD - 1);
    const int b  = ch >> 10;                 // DD = 1024 = 2^10
    const float ew = expf(-expf(td[d]));
    const float* p = kv + ((size_t)b * SS + (size_t)c * CHLEN) * DD + d;
    float s = 0.f;
    #pragma unroll 8
    for (int t = 0; t < CHLEN; t++)
        s = ew * s + p[t * DD];
    carry[idx] = s;
}

__global__ void scan_pass2(const float* __restrict__ carry,
                           float* __restrict__ carryin,
                           const float* __restrict__ td)
{
    const int ch = blockIdx.x * blockDim.x + threadIdx.x;  // 0..NCH-1
    const int d = ch & (DD - 1);
    const float ew = expf(-expf(td[d]));
    float ewL = ew;
    #pragma unroll
    for (int i = 0; i < 6; i++) ewL *= ewL;  // ew^64 = ew^CHLEN
    float s = 0.f;
    for (int c = 0; c < NCHUNK; c++) {
        carryin[c * NCH + ch] = s;
        s = ewL * s + carry[c * NCH + ch];
    }
}

__global__ void scan_pass3(const float* __restrict__ kv,
                           const float* __restrict__ r,
                           const float* __restrict__ td,
                           const float* __restrict__ tf,
                           const float* __restrict__ carryin,
                           float* __restrict__ rw)
{
    const int idx = blockIdx.x * blockDim.x + threadIdx.x;
    const int ch = idx & (NCH - 1);
    const int c  = idx >> 12;
    const int d  = ch & (DD - 1);
    const int b  = ch >> 10;
    const float ew = expf(-expf(td[d]));
    const float eu = expf(tf[d]);
    float s = carryin[idx];
    const size_t base = ((size_t)b * SS + (size_t)c * CHLEN) * DD + d;
    #pragma unroll 8
    for (int t = 0; t < CHLEN; t++) {
        const size_t o = base + (size_t)t * DD;
        float kvt = kv[o];
        float wkv = s + eu * kvt;
        rw[o] = r[o] * wkv;
        s = ew * s + kvt;
    }
}

// ---------------------------------------------------------------------------
// Launch
// ---------------------------------------------------------------------------
static float* symptr(const void* sym)
{
    void* p = nullptr;
    cudaGetSymbolAddress(&p, sym);
    return (float*)p;
}

extern "C" void kernel_launch(void* const* d_in, const int* in_sizes, int n_in,
                              void* d_out, int out_size)
{
    const float* x      = (const float*)d_in[0];
    const float* Wk     = (const float*)d_in[1];
    const float* Wv     = (const float*)d_in[2];
    const float* Wr     = (const float*)d_in[3];
    const float* Wo     = (const float*)d_in[4];
    const float* td     = (const float*)d_in[5];   // time_decay
    const float* tf     = (const float*)d_in[6];   // time_first
    const float* mxs    = (const float*)d_in[7];   // mixer_scale
    const float* Wfc    = (const float*)d_in[8];
    const float* Wmlp   = (const float*)d_in[9];
    const float* mls    = (const float*)d_in[10];  // mlp_scale
    float* out = (float*)d_out;

    float* normed  = symptr(g_normed);
    float* kbuf    = symptr(g_k);
    float* kvbuf   = symptr(g_kv);
    float* rbuf    = symptr(g_r);
    float* x1      = symptr(g_x1);
    float* h2      = symptr(g_h2);
    float* carry   = symptr(g_carry);
    float* carryin = symptr(g_carryin);

    const dim3 gD(DD / 128, MM / 128);   // N=1024 GEMMs
    const dim3 gH(HH / 128, MM / 128);   // N=4096 GEMM

    // 1. normed = RMS(x)
    rms_kernel<<<MM, 256>>>(x, normed);
    // 2. k = normed @ Wk^T
    sgemm_kernel<0><<<gD, 256>>>(normed, Wk, kbuf, MM, DD, DD, nullptr, nullptr);
    // 3. kv = (normed @ Wv^T) * k
    sgemm_kernel<1><<<gD, 256>>>(normed, Wv, kvbuf, MM, DD, DD, kbuf, nullptr);
    // 4. r = sigmoid(normed @ Wr^T)
    sgemm_kernel<2><<<gD, 256>>>(normed, Wr, rbuf, MM, DD, DD, nullptr, nullptr);
    // 5-7. chunked scan; rw = r * wkv  (written into kbuf)
    scan_pass1<<<(NCHUNK * NCH) / 256, 256>>>(kvbuf, td, carry);
    scan_pass2<<<NCH / 256, 256>>>(carry, carryin, td);
    scan_pass3<<<(NCHUNK * NCH) / 256, 256>>>(kvbuf, rbuf, td, tf, carryin, kbuf);
    // 8. x1 = x + mixer_scale * (rw @ Wo^T)
    sgemm_kernel<4><<<gD, 256>>>(kbuf, Wo, x1, MM, DD, DD, x, mxs);
    // 9. normed = RMS(x1)
    rms_kernel<<<MM, 256>>>(x1, normed);
    // 10. h2 = leaky(normed @ Wfc^T, 0.5)^2
    sgemm_kernel<3><<<gH, 256>>>(normed, Wfc, h2, MM, HH, DD, nullptr, nullptr);
    // 11. out = x1 + mlp_scale * (h2 @ Wmlp^T)
    sgemm_kernel<4><<<gD, 256>>>(h2, Wmlp, out, MM, DD, HH, x1, mls);
}